// round 6
// baseline (speedup 1.0000x reference)
#include <cuda_runtime.h>

// Problem constants (match reference)
#define BB   16
#define CC   32
#define HW   384
#define NKK  32
#define HID  128
#define KOUT (NKK * 9)   // 288
#define NSLICE 8

// Conv strip geometry: each warp covers 128 cols x SR rows of one plane.
#define SR   32
#define STRIPS_PER_PLANE (3 * (HW / SR))   // 36
#define CONV_BLOCKS_PER_SAMPLE (NKK * STRIPS_PER_PLANE / 8)  // 144

// Scratch (no allocations allowed in kernel_launch)
__device__ float g_part[BB * CC * NSLICE];  // partial sums per plane slice
__device__ float g_kern[BB * NKK * 9];      // [B, NK, 3, 3] generated kernels
__device__ int   g_cnt[BB];                 // arrival counters (self-resetting)

// ---------------------------------------------------------------------------
// Kernel 1: pool + fused MLP for ONE sample. grid = (C, NSLICE) = 256 CTAs.
// Each CTA sums its slice of one plane; the LAST CTA to finish (atomic
// counter) reduces all partials and runs the kernel-generator MLP inline,
// then resets the counter (replay-safe).
// Default cache policy on loads: fills L2 so the conv pass hits.
// ---------------------------------------------------------------------------
__global__ __launch_bounds__(256)
void poolmlp_kernel(const float* __restrict__ x,
                    const float* __restrict__ w1, const float* __restrict__ b1,
                    const float* __restrict__ w2, const float* __restrict__ b2,
                    int b) {
    const int ch    = blockIdx.x;
    const int slice = blockIdx.y;
    const int bc    = b * CC + ch;
    const int n4    = HW * HW / 4 / NSLICE;           // 4608 float4 per slice
    const float4* p = (const float4*)(x + (size_t)bc * HW * HW) + slice * n4;

    float sum = 0.f;
    #pragma unroll 4
    for (int i = threadIdx.x; i < n4; i += blockDim.x) {
        float4 v = p[i];
        sum += (v.x + v.y) + (v.z + v.w);
    }

    __shared__ float red[8];
    #pragma unroll
    for (int o = 16; o; o >>= 1) sum += __shfl_xor_sync(0xffffffffu, sum, o);
    if ((threadIdx.x & 31) == 0) red[threadIdx.x >> 5] = sum;
    __syncthreads();
    if (threadIdx.x < 32) {
        float s = (threadIdx.x < (blockDim.x >> 5)) ? red[threadIdx.x] : 0.f;
        #pragma unroll
        for (int o = 4; o; o >>= 1) s += __shfl_xor_sync(0xffffffffu, s, o);
        if (threadIdx.x == 0) red[0] = s;
    }
    __syncthreads();

    // Publish partial, then arrive.
    __shared__ int is_last;
    if (threadIdx.x == 0) {
        g_part[bc * NSLICE + slice] = red[0];
        __threadfence();                               // release partial
        int c = atomicAdd(&g_cnt[b], 1);
        is_last = (c == CC * NSLICE - 1);
    }
    __syncthreads();
    if (!is_last) return;

    // ---- Last CTA: reduce partials + MLP ----
    __threadfence();                                   // acquire all partials
    __shared__ float pooled_s[CC];
    __shared__ float hdn_s[HID];
    const int t = threadIdx.x;

    if (t < CC) {
        const float* pp = g_part + (b * CC + t) * NSLICE;
        float s = 0.f;
        #pragma unroll
        for (int i = 0; i < NSLICE; i++) s += pp[i];
        pooled_s[t] = s * (1.f / (float)(HW * HW));
    }
    __syncthreads();

    if (t < HID) {
        float acc = b1[t];
        #pragma unroll 8
        for (int i = 0; i < CC; i++) acc = fmaf(pooled_s[i], w1[i * HID + t], acc);
        hdn_s[t] = fmaxf(acc, 0.f);
    }
    __syncthreads();

    for (int tt = t; tt < KOUT; tt += 256) {
        float acc = b2[tt];
        #pragma unroll 8
        for (int i = 0; i < HID; i++) acc = fmaf(hdn_s[i], w2[i * KOUT + tt], acc);
        g_kern[b * KOUT + tt] = acc;
    }

    if (t == 0) g_cnt[b] = 0;                          // self-reset for next replay
}

// ---------------------------------------------------------------------------
// Kernel 2: depthwise 3x3 conv for ONE sample (32 planes), pad=1.
// Direct-gmem rolling-register strips. Loads __ldcs (last-use; expected L2
// hits from the pool pass). Stores __stcs (streaming).
// ---------------------------------------------------------------------------
struct RowV { float l; float4 c; float r; };

__device__ __forceinline__ RowV load_row(const float* __restrict__ ip,
                                         int y, int gcol) {
    RowV v;
    if ((unsigned)y < (unsigned)HW) {
        const float* rp = ip + (size_t)y * HW + gcol;
        v.c = __ldcs((const float4*)rp);
        v.l = (gcol > 0)        ? __ldcs(rp - 1) : 0.f;
        v.r = (gcol + 4 < HW)   ? __ldcs(rp + 4) : 0.f;
    } else {
        v.c = make_float4(0.f, 0.f, 0.f, 0.f);
        v.l = 0.f; v.r = 0.f;
    }
    return v;
}

__device__ __forceinline__ void accum_row(float4& acc, const RowV& v,
                                          float w0, float w1, float w2) {
    acc.x = fmaf(w0, v.l,   fmaf(w1, v.c.x, fmaf(w2, v.c.y, acc.x)));
    acc.y = fmaf(w0, v.c.x, fmaf(w1, v.c.y, fmaf(w2, v.c.z, acc.y)));
    acc.z = fmaf(w0, v.c.y, fmaf(w1, v.c.z, fmaf(w2, v.c.w, acc.z)));
    acc.w = fmaf(w0, v.c.z, fmaf(w1, v.c.w, fmaf(w2, v.r,   acc.w)));
}

__global__ __launch_bounds__(256)
void conv_kernel(const float* __restrict__ x, float* __restrict__ out, int b) {
    const int wid  = (blockIdx.x << 3) + (threadIdx.x >> 5);  // warp id in sample
    const int lane = threadIdx.x & 31;

    const int nk   = wid / STRIPS_PER_PLANE;           // 0..31 (plane)
    const int rem  = wid % STRIPS_PER_PLANE;           // 0..35
    const int cstrip = rem % 3;
    const int rstrip = rem / 3;

    const int plane = b * NKK + nk;
    const int gcol  = cstrip * 128 + lane * 4;
    const int r0    = rstrip * SR;

    const float* __restrict__ ip = x   + ((size_t)b * CC + nk) * (size_t)(HW * HW);
    float*       __restrict__ op = out + (size_t)plane * (size_t)(HW * HW) + gcol;

    float w[9];
    {
        const float* kp = g_kern + plane * 9;
        #pragma unroll
        for (int i = 0; i < 9; i++) w[i] = kp[i];
    }

    RowV a  = load_row(ip, r0 - 1, gcol);
    RowV bb = load_row(ip, r0,     gcol);
    RowV c  = load_row(ip, r0 + 1, gcol);

    #pragma unroll 4
    for (int i = 0; i < SR; i++) {
        RowV d = load_row(ip, r0 + 2 + i, gcol);   // prefetch next (guarded OOB)
        float4 acc = make_float4(0.f, 0.f, 0.f, 0.f);
        accum_row(acc, a,  w[0], w[1], w[2]);
        accum_row(acc, bb, w[3], w[4], w[5]);
        accum_row(acc, c,  w[6], w[7], w[8]);
        __stcs((float4*)(op + (size_t)(r0 + i) * HW), acc);
        a = bb; bb = c; c = d;
    }
}

// ---------------------------------------------------------------------------
// Single-stream per-sample interleave:
//   poolmlp(0), poolmlp(1), conv(0), poolmlp(2), conv(1), ..., conv(15)
// conv(b) runs right after sample b entered L2 (window = 2 samples ~38MB),
// so its reads are L2 hits and only the output write touches DRAM.
// ---------------------------------------------------------------------------
extern "C" void kernel_launch(void* const* d_in, const int* in_sizes, int n_in,
                              void* d_out, int out_size) {
    const float* x  = (const float*)d_in[0];
    const float* w1 = (const float*)d_in[1];
    const float* b1 = (const float*)d_in[2];
    const float* w2 = (const float*)d_in[3];
    const float* b2 = (const float*)d_in[4];
    float* out = (float*)d_out;

    poolmlp_kernel<<<dim3(CC, NSLICE), 256>>>(x, w1, b1, w2, b2, 0);
    for (int b = 0; b < BB; b++) {
        if (b + 1 < BB)
            poolmlp_kernel<<<dim3(CC, NSLICE), 256>>>(x, w1, b1, w2, b2, b + 1);
        conv_kernel<<<CONV_BLOCKS_PER_SAMPLE, 256>>>(x, out, b);
    }
}

// round 7
// speedup vs baseline: 2.5559x; 2.5559x over previous
#include <cuda_runtime.h>

// Problem constants (match reference)
#define BB   16
#define CC   32
#define HW   384
#define NKK  32
#define HID  128
#define KOUT (NKK * 9)   // 288
#define NSLICE 4
#define ARRIVALS (CC * NSLICE)   // pool CTAs per sample = 128

// Conv strip geometry: each warp covers 128 cols x SR rows of one plane.
#define SR   32
#define STRIPS_PER_PLANE (3 * (HW / SR))   // 36
#define TOTAL_STRIPS (BB * NKK * STRIPS_PER_PLANE)  // 18432 warps

// Scratch (no allocations allowed in kernel_launch)
__device__ float g_part[BB * CC * NSLICE];  // partial sums per plane slice
__device__ float g_kern[BB * NKK * 9];      // [B, NK, 3, 3] generated kernels
__device__ int   g_cnt[BB];                 // per-sample arrival counters (self-reset)

// ---------------------------------------------------------------------------
// Kernel 1: monolithic pool + fused per-sample MLP.
// grid = (B*C, NSLICE) = 2048 CTAs (proven 6.5 TB/s). Each CTA sums its
// quarter-plane; the last CTA of each sample (atomic counter) reduces the
// sample's 128 partials and runs the kernel-generator MLP inline.
// Default-cached loads fill L2 for the conv pass.
// ---------------------------------------------------------------------------
__global__ __launch_bounds__(256)
void pool_fused_kernel(const float* __restrict__ x,
                       const float* __restrict__ w1, const float* __restrict__ b1,
                       const float* __restrict__ w2, const float* __restrict__ b2) {
    const int bc    = blockIdx.x;                     // 0..511
    const int b     = bc >> 5;
    const int slice = blockIdx.y;
    const int n4    = HW * HW / 4 / NSLICE;           // 9216 float4 per slice
    const float4* p = (const float4*)(x + (size_t)bc * HW * HW) + slice * n4;

    float sum = 0.f;
    #pragma unroll 4
    for (int i = threadIdx.x; i < n4; i += blockDim.x) {
        float4 v = p[i];
        sum += (v.x + v.y) + (v.z + v.w);
    }

    __shared__ float red[8];
    #pragma unroll
    for (int o = 16; o; o >>= 1) sum += __shfl_xor_sync(0xffffffffu, sum, o);
    if ((threadIdx.x & 31) == 0) red[threadIdx.x >> 5] = sum;
    __syncthreads();
    if (threadIdx.x < 32) {
        float s = (threadIdx.x < (blockDim.x >> 5)) ? red[threadIdx.x] : 0.f;
        #pragma unroll
        for (int o = 4; o; o >>= 1) s += __shfl_xor_sync(0xffffffffu, s, o);
        if (threadIdx.x == 0) red[0] = s;
    }
    __syncthreads();

    // Publish partial, then arrive on this sample's counter.
    __shared__ int is_last;
    if (threadIdx.x == 0) {
        g_part[bc * NSLICE + slice] = red[0];
        __threadfence();                               // release partial
        int c = atomicAdd(&g_cnt[b], 1);
        is_last = (c == ARRIVALS - 1);
    }
    __syncthreads();
    if (!is_last) return;

    // ---- Last CTA of sample b: reduce partials + MLP ----
    __threadfence();                                   // acquire all partials
    __shared__ float pooled_s[CC];
    __shared__ float hdn_s[HID];
    const int t = threadIdx.x;

    if (t < CC) {
        const float* pp = g_part + (b * CC + t) * NSLICE;
        float s = 0.f;
        #pragma unroll
        for (int i = 0; i < NSLICE; i++) s += pp[i];
        pooled_s[t] = s * (1.f / (float)(HW * HW));
    }
    __syncthreads();

    if (t < HID) {
        float acc = b1[t];
        #pragma unroll 8
        for (int i = 0; i < CC; i++) acc = fmaf(pooled_s[i], w1[i * HID + t], acc);
        hdn_s[t] = fmaxf(acc, 0.f);
    }
    __syncthreads();

    for (int tt = t; tt < KOUT; tt += 256) {
        float acc = b2[tt];
        #pragma unroll 8
        for (int i = 0; i < HID; i++) acc = fmaf(hdn_s[i], w2[i * KOUT + tt], acc);
        g_kern[b * KOUT + tt] = acc;
    }

    if (t == 0) g_cnt[b] = 0;                          // self-reset for replays
}

// ---------------------------------------------------------------------------
// Kernel 2: monolithic depthwise 3x3 conv, pad=1.
// Direct-gmem rolling-register strips (R4-proven). Warp->strip mapping is
// REVERSED in global address order: conv starts where pool finished, so its
// first ~100MB of reads hit the L2 residue left by the pool pass.
// Plain cached loads (halo reuse), streaming stores.
// ---------------------------------------------------------------------------
struct RowV { float l; float4 c; float r; };

__device__ __forceinline__ RowV load_row(const float* __restrict__ ip,
                                         int y, int gcol) {
    RowV v;
    if ((unsigned)y < (unsigned)HW) {
        const float* rp = ip + (size_t)y * HW + gcol;
        v.c = *(const float4*)rp;
        v.l = (gcol > 0)        ? rp[-1] : 0.f;
        v.r = (gcol + 4 < HW)   ? rp[4]  : 0.f;
    } else {
        v.c = make_float4(0.f, 0.f, 0.f, 0.f);
        v.l = 0.f; v.r = 0.f;
    }
    return v;
}

__device__ __forceinline__ void accum_row(float4& acc, const RowV& v,
                                          float w0, float w1, float w2) {
    acc.x = fmaf(w0, v.l,   fmaf(w1, v.c.x, fmaf(w2, v.c.y, acc.x)));
    acc.y = fmaf(w0, v.c.x, fmaf(w1, v.c.y, fmaf(w2, v.c.z, acc.y)));
    acc.z = fmaf(w0, v.c.y, fmaf(w1, v.c.z, fmaf(w2, v.c.w, acc.z)));
    acc.w = fmaf(w0, v.c.z, fmaf(w1, v.c.w, fmaf(w2, v.r,   acc.w)));
}

__global__ __launch_bounds__(256)
void conv_kernel(const float* __restrict__ x, float* __restrict__ out) {
    // Reverse global strip order: first-launched blocks touch the highest
    // addresses (= pool's freshest L2 lines).
    const int wid_f = (blockIdx.x << 3) + (threadIdx.x >> 5);
    const int wid   = TOTAL_STRIPS - 1 - wid_f;
    const int lane  = threadIdx.x & 31;

    const int plane = wid / STRIPS_PER_PLANE;          // 0..511
    const int rem   = wid % STRIPS_PER_PLANE;          // 0..35
    const int rstrip = rem / 3;                        // row-major within plane
    const int cstrip = rem % 3;

    const int b  = plane >> 5;
    const int ch = plane & 31;
    const int gcol = cstrip * 128 + lane * 4;
    const int r0   = rstrip * SR;

    const float* __restrict__ ip = x   + ((size_t)b * CC + ch) * (size_t)(HW * HW);
    float*       __restrict__ op = out + (size_t)plane * (size_t)(HW * HW) + gcol;

    float w[9];
    {
        const float* kp = g_kern + plane * 9;
        #pragma unroll
        for (int i = 0; i < 9; i++) w[i] = kp[i];
    }

    RowV a  = load_row(ip, r0 - 1, gcol);
    RowV bb = load_row(ip, r0,     gcol);
    RowV c  = load_row(ip, r0 + 1, gcol);

    #pragma unroll 4
    for (int i = 0; i < SR; i++) {
        RowV d = load_row(ip, r0 + 2 + i, gcol);   // prefetch next (guarded OOB)
        float4 acc = make_float4(0.f, 0.f, 0.f, 0.f);
        accum_row(acc, a,  w[0], w[1], w[2]);
        accum_row(acc, bb, w[3], w[4], w[5]);
        accum_row(acc, c,  w[6], w[7], w[8]);
        __stcs((float4*)(op + (size_t)(r0 + i) * HW), acc);
        a = bb; bb = c; c = d;
    }
}

// ---------------------------------------------------------------------------
extern "C" void kernel_launch(void* const* d_in, const int* in_sizes, int n_in,
                              void* d_out, int out_size) {
    const float* x  = (const float*)d_in[0];
    const float* w1 = (const float*)d_in[1];
    const float* b1 = (const float*)d_in[2];
    const float* w2 = (const float*)d_in[3];
    const float* b2 = (const float*)d_in[4];
    float* out = (float*)d_out;

    pool_fused_kernel<<<dim3(BB * CC, NSLICE), 256>>>(x, w1, b1, w2, b2);
    conv_kernel<<<TOTAL_STRIPS / 8, 256>>>(x, out);
}

// round 8
// speedup vs baseline: 2.6845x; 1.0503x over previous
#include <cuda_runtime.h>

// Problem constants (match reference)
#define BB   16
#define CC   32
#define HW   384
#define NKK  32
#define HID  128
#define KOUT (NKK * 9)   // 288
#define NSLICE 4

// Conv strip geometry: each warp covers 128 cols x SR rows of one plane.
#define SR   32
#define STRIPS_PER_PLANE (3 * (HW / SR))   // 36
#define TOTAL_STRIPS (BB * NKK * STRIPS_PER_PLANE)  // 18432 warps

// Scratch (no allocations allowed in kernel_launch)
__device__ float g_part[BB * CC * NSLICE];  // partial sums per plane slice
__device__ float g_kern[BB * NKK * 9];      // [B, NK, 3, 3] generated kernels

// ---------------------------------------------------------------------------
// Kernel 1: partial average pool (R4-proven: 46.8us @ 6.5TB/s).
// grid = (B*C, NSLICE) = 2048 CTAs. Default-cached loads fill L2.
// ---------------------------------------------------------------------------
__global__ void pool_kernel(const float* __restrict__ x) {
    const int bc    = blockIdx.x;
    const int slice = blockIdx.y;
    const int n4    = HW * HW / 4 / NSLICE;           // 9216 float4 per slice
    const float4* p = (const float4*)(x + (size_t)bc * HW * HW) + slice * n4;

    float sum = 0.f;
    #pragma unroll 4
    for (int i = threadIdx.x; i < n4; i += blockDim.x) {
        float4 v = p[i];
        sum += (v.x + v.y) + (v.z + v.w);
    }

    __shared__ float red[8];
    #pragma unroll
    for (int o = 16; o; o >>= 1) sum += __shfl_xor_sync(0xffffffffu, sum, o);
    if ((threadIdx.x & 31) == 0) red[threadIdx.x >> 5] = sum;
    __syncthreads();
    if (threadIdx.x < 32) {
        float s = (threadIdx.x < (blockDim.x >> 5)) ? red[threadIdx.x] : 0.f;
        #pragma unroll
        for (int o = 4; o; o >>= 1) s += __shfl_xor_sync(0xffffffffu, s, o);
        if (threadIdx.x == 0) g_part[bc * NSLICE + slice] = s;
    }
}

// ---------------------------------------------------------------------------
// Kernel 2: reduce partials + tiny MLP -> per-sample depthwise kernels
// ---------------------------------------------------------------------------
__global__ void mlp_kernel(const float* __restrict__ w1, const float* __restrict__ b1,
                           const float* __restrict__ w2, const float* __restrict__ b2) {
    const int b = blockIdx.x;
    const int t = threadIdx.x;

    __shared__ float pooled_s[CC];
    __shared__ float hdn_s[HID];

    if (t < CC) {
        const float* pp = g_part + (b * CC + t) * NSLICE;
        pooled_s[t] = (pp[0] + pp[1] + pp[2] + pp[3]) * (1.f / (float)(HW * HW));
    }
    __syncthreads();

    if (t < HID) {
        float acc = b1[t];
        #pragma unroll 8
        for (int i = 0; i < CC; i++) acc = fmaf(pooled_s[i], w1[i * HID + t], acc);
        hdn_s[t] = fmaxf(acc, 0.f);
    }
    __syncthreads();

    if (t < KOUT) {
        float acc = b2[t];
        #pragma unroll 8
        for (int i = 0; i < HID; i++) acc = fmaf(hdn_s[i], w2[i * KOUT + t], acc);
        g_kern[b * KOUT + t] = acc;
    }
}

// ---------------------------------------------------------------------------
// Kernel 3: monolithic depthwise 3x3 conv, pad=1 (R7 conv, unchanged).
// Direct-gmem rolling-register strips; warp->strip mapping REVERSED in
// global address order so conv starts on pool's freshest L2 lines.
// ---------------------------------------------------------------------------
struct RowV { float l; float4 c; float r; };

__device__ __forceinline__ RowV load_row(const float* __restrict__ ip,
                                         int y, int gcol) {
    RowV v;
    if ((unsigned)y < (unsigned)HW) {
        const float* rp = ip + (size_t)y * HW + gcol;
        v.c = *(const float4*)rp;
        v.l = (gcol > 0)        ? rp[-1] : 0.f;
        v.r = (gcol + 4 < HW)   ? rp[4]  : 0.f;
    } else {
        v.c = make_float4(0.f, 0.f, 0.f, 0.f);
        v.l = 0.f; v.r = 0.f;
    }
    return v;
}

__device__ __forceinline__ void accum_row(float4& acc, const RowV& v,
                                          float w0, float w1, float w2) {
    acc.x = fmaf(w0, v.l,   fmaf(w1, v.c.x, fmaf(w2, v.c.y, acc.x)));
    acc.y = fmaf(w0, v.c.x, fmaf(w1, v.c.y, fmaf(w2, v.c.z, acc.y)));
    acc.z = fmaf(w0, v.c.y, fmaf(w1, v.c.z, fmaf(w2, v.c.w, acc.z)));
    acc.w = fmaf(w0, v.c.z, fmaf(w1, v.c.w, fmaf(w2, v.r,   acc.w)));
}

__global__ __launch_bounds__(256)
void conv_kernel(const float* __restrict__ x, float* __restrict__ out) {
    const int wid_f = (blockIdx.x << 3) + (threadIdx.x >> 5);
    const int wid   = TOTAL_STRIPS - 1 - wid_f;        // reversed address order
    const int lane  = threadIdx.x & 31;

    const int plane = wid / STRIPS_PER_PLANE;          // 0..511
    const int rem   = wid % STRIPS_PER_PLANE;          // 0..35
    const int rstrip = rem / 3;
    const int cstrip = rem % 3;

    const int b  = plane >> 5;
    const int ch = plane & 31;
    const int gcol = cstrip * 128 + lane * 4;
    const int r0   = rstrip * SR;

    const float* __restrict__ ip = x   + ((size_t)b * CC + ch) * (size_t)(HW * HW);
    float*       __restrict__ op = out + (size_t)plane * (size_t)(HW * HW) + gcol;

    float w[9];
    {
        const float* kp = g_kern + plane * 9;
        #pragma unroll
        for (int i = 0; i < 9; i++) w[i] = kp[i];
    }

    RowV a  = load_row(ip, r0 - 1, gcol);
    RowV bb = load_row(ip, r0,     gcol);
    RowV c  = load_row(ip, r0 + 1, gcol);

    #pragma unroll 4
    for (int i = 0; i < SR; i++) {
        RowV d = load_row(ip, r0 + 2 + i, gcol);   // prefetch next (guarded OOB)
        float4 acc = make_float4(0.f, 0.f, 0.f, 0.f);
        accum_row(acc, a,  w[0], w[1], w[2]);
        accum_row(acc, bb, w[3], w[4], w[5]);
        accum_row(acc, c,  w[6], w[7], w[8]);
        __stcs((float4*)(op + (size_t)(r0 + i) * HW), acc);
        a = bb; bb = c; c = d;
    }
}

// ---------------------------------------------------------------------------
extern "C" void kernel_launch(void* const* d_in, const int* in_sizes, int n_in,
                              void* d_out, int out_size) {
    const float* x  = (const float*)d_in[0];
    const float* w1 = (const float*)d_in[1];
    const float* b1 = (const float*)d_in[2];
    const float* w2 = (const float*)d_in[3];
    const float* b2 = (const float*)d_in[4];
    float* out = (float*)d_out;

    pool_kernel<<<dim3(BB * CC, NSLICE), 256>>>(x);
    mlp_kernel<<<BB, KOUT>>>(w1, b1, w2, b2);
    conv_kernel<<<TOTAL_STRIPS / 8, 256>>>(x, out);
}